// round 13
// baseline (speedup 1.0000x reference)
#include <cuda_runtime.h>
#include <math.h>

#define BB 32
#define TT 1024
#define VV 5000
#define STEPS 64
#define JPAD 5008
#define NP 32            // attention T-parts
#define GKS 8            // gates K-split (chunk 192)
#define LKS 4            // logits K-split

// ---------------- persistent device state ----------------
__device__ float g_actT[1536 * BB];          // [emb|ctx|h] transposed [k][b]
__device__ float g_hcT[1024 * BB];           // [h|ctx] transposed
__device__ float g_hRow[BB * 512];           // h row-major [b][i]
__device__ float g_cT[512 * BB];
__device__ float g_gatesP[GKS][2048 * BB];
__device__ float g_hidT[512 * BB];
__device__ float g_logitsP[LKS][BB * JPAD];
__device__ float g_eBuf[BB * TT];
__device__ float g_mP[NP * 128];
__device__ float g_sP[NP * 128];
__device__ float g_ctxP[NP][128 * 128];
__device__ unsigned g_cntA[128];             // per-ig counters (gates)
__device__ unsigned g_cntB[128];             // per-bh counters (attention)

// ---------------- init ----------------
__global__ void init_kernel(const float* __restrict__ emb, const float* __restrict__ lf)
{
    int idx = blockIdx.x * blockDim.x + threadIdx.x;
    if (idx >= 1536 * BB) return;
    int b = idx & 31, k = idx >> 5;
    float v;
    if (k < 512)       v = emb[k];
    else if (k < 1024) v = lf[(size_t)b * TT * 512 + (k - 512)];
    else             { v = 0.f; g_cT[(k - 1024) * BB + b] = 0.f; }
    g_actT[idx] = v;
}

// ====== gates GEMM (gate-aligned tiles) + fused LSTM pointwise tail ======
// block (ig, part): 16 rows j = gate*512 + ig*4 + il, K-chunk part*192..+192
__global__ void gates_gemm_kernel(const float* __restrict__ W_ih,
                                  const float* __restrict__ W_hh,
                                  const float* __restrict__ b_ih,
                                  const float* __restrict__ b_hh)
{
    __shared__ float ws[16 * 193];
    __shared__ int s_last;
    const int ig = blockIdx.x;          // 0..127
    const int part = blockIdx.y;        // 0..7
    const int base = part * 192;
    const int tid = threadIdx.x;        // 128

    for (int idx = tid; idx < 16 * 192; idx += 128) {
        int r = idx / 192, kk = idx - r * 192;
        int j = (r >> 2) * 512 + ig * 4 + (r & 3);
        int k = base + kk;
        ws[r * 193 + kk] = (k < 1024) ? W_ih[(size_t)j * 1024 + k]
                                      : W_hh[(size_t)j * 512 + (k - 1024)];
    }
    __syncthreads();

    int bg = tid & 7, jj = tid >> 3;
    int j = (jj >> 2) * 512 + ig * 4 + (jj & 3);
    const float* wr = ws + jj * 193;
    const float4* xv = (const float4*)g_actT;
    float ax = 0.f, ay = 0.f, az = 0.f, aw = 0.f;
    #pragma unroll 8
    for (int kk = 0; kk < 192; kk++) {
        float w = wr[kk];
        float4 x = xv[(base + kk) * 8 + bg];
        ax = fmaf(w, x.x, ax); ay = fmaf(w, x.y, ay);
        az = fmaf(w, x.z, az); aw = fmaf(w, x.w, aw);
    }
    ((float4*)g_gatesP[part])[j * 8 + bg] = make_float4(ax, ay, az, aw);

    // ---- last-arrival tail: LSTM pointwise for i in [ig*4, ig*4+4) ----
    __syncthreads();
    __threadfence();
    if (tid == 0) {
        unsigned r = atomicAdd(&g_cntA[ig], 1u);
        s_last = (r == GKS - 1);
        if (s_last) g_cntA[ig] = 0u;   // sole executor; next use is stream-ordered
    }
    __syncthreads();
    if (s_last) {
        int isub = tid >> 5, b = tid & 31;
        int i = ig * 4 + isub;
        float g4[4];
        #pragma unroll
        for (int g = 0; g < 4; g++) {
            int jg = g * 512 + i;
            float v = b_ih[jg] + b_hh[jg];
            #pragma unroll
            for (int p = 0; p < GKS; p++) v += g_gatesP[p][jg * 32 + b];
            g4[g] = v;
        }
        float si = 1.f / (1.f + __expf(-g4[0]));
        float sf = 1.f / (1.f + __expf(-g4[1]));
        float tg = tanhf(g4[2]);
        float so = 1.f / (1.f + __expf(-g4[3]));
        float c = sf * g_cT[i * 32 + b] + si * tg;
        g_cT[i * 32 + b] = c;
        float h = so * tanhf(c);
        g_hRow[b * 512 + i] = h;
        g_hcT[i * 32 + b] = h;
        g_actT[(1024 + i) * 32 + b] = h;
    }
}

// ====== attention partials (512 thr, warp = 2 t) + fused combine tail ======
__global__ void __launch_bounds__(512, 3)
attn_part_kernel(const float* __restrict__ lf, float* __restrict__ attn_out)
{
    __shared__ float e_s[32];
    __shared__ __align__(16) float csh[16 * 132];
    __shared__ float w_s[NP];
    __shared__ float Ms, Ss;
    __shared__ int s_last;

    int b = blockIdx.x & 31, hh = blockIdx.x >> 5;
    int part = blockIdx.y;
    int t0 = part * 32;
    int tid = threadIdx.x, lane = tid & 31, w = tid >> 5;   // 16 warps
    int bh = b * 4 + hh;

    float4 ds4 = ((const float4*)(g_hRow + b * 512 + hh * 128))[lane];

    const float4* src = (const float4*)(lf + ((size_t)b * TT + t0) * 512 + hh * 128);
    float4 v0 = src[(size_t)(w * 2 + 0) * 128 + lane];
    float4 v1 = src[(size_t)(w * 2 + 1) * 128 + lane];

    float a0 = ds4.x * v0.x + ds4.y * v0.y + ds4.z * v0.z + ds4.w * v0.w;
    float a1 = ds4.x * v1.x + ds4.y * v1.y + ds4.z * v1.z + ds4.w * v1.w;
    #pragma unroll
    for (int off = 16; off; off >>= 1) {
        a0 += __shfl_xor_sync(~0u, a0, off);
        a1 += __shfl_xor_sync(~0u, a1, off);
    }
    if (lane == 0) { e_s[w * 2] = a0; e_s[w * 2 + 1] = a1; }
    __syncthreads();

    if (tid < 32) {
        float e = e_s[tid];
        if (hh == 3) g_eBuf[b * TT + t0 + tid] = e;
        float m = e;
        #pragma unroll
        for (int off = 16; off; off >>= 1) m = fmaxf(m, __shfl_xor_sync(~0u, m, off));
        float p = __expf(e - m);
        e_s[tid] = p;
        float s = p;
        #pragma unroll
        for (int off = 16; off; off >>= 1) s += __shfl_xor_sync(~0u, s, off);
        if (tid == 0) { g_mP[part * 128 + bh] = m; g_sP[part * 128 + bh] = s; }
    }
    __syncthreads();

    {   // context partial in registers
        float p0 = e_s[w * 2], p1 = e_s[w * 2 + 1];
        float4 acc;
        acc.x = p0 * v0.x + p1 * v1.x;
        acc.y = p0 * v0.y + p1 * v1.y;
        acc.z = p0 * v0.z + p1 * v1.z;
        acc.w = p0 * v0.w + p1 * v1.w;
        ((float4*)&csh[w * 132])[lane] = acc;
    }
    __syncthreads();
    if (tid < 128) {
        float ss = 0.f;
        #pragma unroll
        for (int q = 0; q < 16; q++) ss += csh[q * 132 + tid];
        g_ctxP[part][bh * 128 + tid] = ss;
    }

    // ---- last-arrival tail: combine for this (b, hh) ----
    __syncthreads();
    __threadfence();
    if (tid == 0) {
        unsigned r = atomicAdd(&g_cntB[bh], 1u);
        s_last = (r == NP - 1);
        if (s_last) g_cntB[bh] = 0u;
    }
    __syncthreads();
    if (!s_last) return;

    if (tid < 32) {
        float m = g_mP[tid * 128 + bh];
        float sp = g_sP[tid * 128 + bh];
        float M = m;
        #pragma unroll
        for (int off = 16; off; off >>= 1) M = fmaxf(M, __shfl_xor_sync(~0u, M, off));
        float wv = __expf(m - M);
        w_s[tid] = wv;
        float s = sp * wv;
        #pragma unroll
        for (int off = 16; off; off >>= 1) s += __shfl_xor_sync(~0u, s, off);
        if (tid == 0) { Ms = M; Ss = s; }
    }
    __syncthreads();
    float inv = 1.f / Ss;
    float M = Ms;

    if (tid < 128) {
        float ctx = 0.f;
        #pragma unroll
        for (int p = 0; p < NP; p++) ctx = fmaf(g_ctxP[p][bh * 128 + tid], w_s[p], ctx);
        ctx *= inv;
        int d = hh * 128 + tid;
        g_actT[(512 + d) * 32 + b] = ctx;
        g_hcT[(512 + d) * 32 + b] = ctx;
    }
    if (hh == 3) {
        int t1 = tid, t2 = tid + 512;
        __stcs(&attn_out[(size_t)b * TT + t1], __expf(g_eBuf[b * TT + t1] - M) * inv);
        __stcs(&attn_out[(size_t)b * TT + t2], __expf(g_eBuf[b * TT + t2] - M) * inv);
    }
}

// ---------------- predict_hid: warp per (j, K-half) ----------------
__global__ void hid_gemm_kernel(const float* __restrict__ Wp, const float* __restrict__ bp)
{
    __shared__ float ph[8][32];
    int wid = threadIdx.x >> 5, lane = threadIdx.x & 31;
    int jj = wid >> 1, half = wid & 1;
    int j = blockIdx.x * 4 + jj;
    const float4* wv = (const float4*)(Wp + (size_t)j * 1024 + half * 512);
    const float* x = g_hcT + half * 512 * BB;
    float acc = 0.f;
    #pragma unroll 8
    for (int k4 = 0; k4 < 128; k4++) {
        float4 wq = wv[k4];
        int k = k4 * 4;
        acc = fmaf(wq.x, x[(k + 0) * BB + lane], acc);
        acc = fmaf(wq.y, x[(k + 1) * BB + lane], acc);
        acc = fmaf(wq.z, x[(k + 2) * BB + lane], acc);
        acc = fmaf(wq.w, x[(k + 3) * BB + lane], acc);
    }
    ph[wid][lane] = acc;
    __syncthreads();
    if (wid < 4) {
        int j2 = blockIdx.x * 4 + wid;
        float v = ph[wid * 2][lane] + ph[wid * 2 + 1][lane] + bp[j2];
        g_hidT[j2 * BB + lane] = fmaxf(v, 0.f);
    }
}

// ---------------- logits GEMM, K-split x4, padded smem ----------------
__global__ void logits_gemm_kernel(const float* __restrict__ Wc)
{
    __shared__ float ws[16 * 129];
    const int j0 = blockIdx.x * 16;
    const int base = blockIdx.y * 128;
    for (int idx = threadIdx.x; idx < 16 * 128; idx += 128) {
        int r = idx >> 7, kk = idx & 127;
        int j = j0 + r;
        ws[r * 129 + kk] = (j < VV) ? Wc[(size_t)j * 512 + base + kk] : 0.f;
    }
    __syncthreads();

    int bg = threadIdx.x & 7, jj = threadIdx.x >> 3;
    int j = j0 + jj;
    const float* wr = ws + jj * 129;
    const float4* xv = (const float4*)g_hidT;
    float ax = 0.f, ay = 0.f, az = 0.f, aw = 0.f;
    #pragma unroll 8
    for (int kk = 0; kk < 128; kk++) {
        float w = wr[kk];
        float4 x = xv[(base + kk) * 8 + bg];
        ax = fmaf(w, x.x, ax); ay = fmaf(w, x.y, ay);
        az = fmaf(w, x.z, az); aw = fmaf(w, x.w, aw);
    }
    if (j < VV) {
        float* dst = g_logitsP[blockIdx.y];
        int b0 = bg * 4;
        dst[(size_t)(b0 + 0) * JPAD + j] = ax;
        dst[(size_t)(b0 + 1) * JPAD + j] = ay;
        dst[(size_t)(b0 + 2) * JPAD + j] = az;
        dst[(size_t)(b0 + 3) * JPAD + j] = aw;
    }
}

// ------- log_softmax + argmax + pred row + next embedding -----
__global__ void lsm_kernel(const float* __restrict__ bc, const float* __restrict__ emb,
                           float* __restrict__ out_pred)
{
    int b = blockIdx.x;
    int tid = threadIdx.x;   // 1024
    __shared__ float v_s[VV];
    __shared__ float sv[1024];
    __shared__ int   si[1024];
    __shared__ int   tok_s;

    const float4* p0 = (const float4*)(g_logitsP[0] + (size_t)b * JPAD);
    const float4* p1 = (const float4*)(g_logitsP[1] + (size_t)b * JPAD);
    const float4* p2 = (const float4*)(g_logitsP[2] + (size_t)b * JPAD);
    const float4* p3 = (const float4*)(g_logitsP[3] + (size_t)b * JPAD);
    const float4* bcv = (const float4*)bc;
    for (int j4 = tid; j4 < VV / 4; j4 += 1024) {
        float4 a = p0[j4], c = p1[j4], d = p2[j4], e = p3[j4], f = bcv[j4];
        float4 r;
        r.x = a.x + c.x + d.x + e.x + f.x;
        r.y = a.y + c.y + d.y + e.y + f.y;
        r.z = a.z + c.z + d.z + e.z + f.z;
        r.w = a.w + c.w + d.w + e.w + f.w;
        ((float4*)v_s)[j4] = r;
    }
    __syncthreads();

    float m = -1e30f; int mi = VV;
    for (int j = tid; j < VV; j += 1024) {
        float v = v_s[j];
        if (v > m) { m = v; mi = j; }
    }
    sv[tid] = m; si[tid] = mi; __syncthreads();
    for (int st = 512; st; st >>= 1) {
        if (tid < st) {
            float v2 = sv[tid + st]; int i2 = si[tid + st];
            if (v2 > sv[tid] || (v2 == sv[tid] && i2 < si[tid])) { sv[tid] = v2; si[tid] = i2; }
        }
        __syncthreads();
    }
    float mm = sv[0];
    if (tid == 0) tok_s = si[0];
    __syncthreads();

    float s = 0.f;
    for (int j = tid; j < VV; j += 1024) s += __expf(v_s[j] - mm);
    sv[tid] = s; __syncthreads();
    for (int st = 512; st; st >>= 1) { if (tid < st) sv[tid] += sv[tid + st]; __syncthreads(); }
    float lse = mm + logf(sv[0]);

    float4* row = (float4*)(out_pred + (size_t)b * VV);
    for (int j4 = tid; j4 < VV / 4; j4 += 1024) {
        float4 v = ((float4*)v_s)[j4];
        v.x -= lse; v.y -= lse; v.z -= lse; v.w -= lse;
        __stcs(&row[j4], v);
    }

    int tok = tok_s;
    if (tid < 512) g_actT[tid * BB + b] = emb[(size_t)tok * 512 + tid];
}

// ---------------- launcher ----------------
extern "C" void kernel_launch(void* const* d_in, const int* in_sizes, int n_in,
                              void* d_out, int out_size)
{
    const float* lf   = (const float*)d_in[0];
    const float* emb  = (const float*)d_in[1];
    const float* W_ih = (const float*)d_in[2];
    const float* W_hh = (const float*)d_in[3];
    const float* b_ih = (const float*)d_in[4];
    const float* b_hh = (const float*)d_in[5];
    const float* Wp   = (const float*)d_in[6];
    const float* bp   = (const float*)d_in[7];
    const float* Wc   = (const float*)d_in[8];
    const float* bc   = (const float*)d_in[9];

    float* out      = (float*)d_out;
    float* out_pred = out;
    float* out_attn = out + (size_t)STEPS * BB * VV;

    init_kernel<<<192, 256>>>(emb, lf);

    for (int s = 0; s < STEPS; s++) {
        gates_gemm_kernel<<<dim3(128, GKS), 128>>>(W_ih, W_hh, b_ih, b_hh);
        attn_part_kernel<<<dim3(128, NP), 512>>>(lf, out_attn + (size_t)s * BB * TT);
        hid_gemm_kernel<<<128, 256>>>(Wp, bp);
        logits_gemm_kernel<<<dim3(313, LKS), 128>>>(Wc);
        lsm_kernel<<<32, 1024>>>(bc, emb, out_pred + (size_t)s * BB * VV);
    }
}

// round 14
// speedup vs baseline: 1.2384x; 1.2384x over previous
#include <cuda_runtime.h>
#include <math.h>

#define BB 32
#define TT 1024
#define VV 5000
#define STEPS 64
#define JPAD 5008
#define NP 32            // attention T-parts
#define TCH 32           // t-chunk per part
#define GKS 8            // gates K-split
#define LKS 4            // logits K-split
#define HKS 8            // hid K-split (chunk 128)

// ---------------- persistent device state ----------------
__device__ float g_actT[1536 * BB];          // [emb|ctx|h] transposed [k][b]
__device__ float g_hcT[1024 * BB];           // [h|ctx] transposed
__device__ float g_hRow[BB * 512];           // h row-major [b][i]
__device__ float g_cT[512 * BB];
__device__ float g_gatesP[GKS][2048 * BB];
__device__ float g_hidP[HKS][512 * BB];      // hid partials [j][b]
__device__ float g_hidT[512 * BB];
__device__ float g_logitsP[LKS][BB * JPAD];
__device__ float g_eBuf[BB * TT];
__device__ float g_mP[NP * 128];
__device__ float g_sP[NP * 128];
__device__ float g_ctxP[NP][128 * 128];

// ---------------- init ----------------
__global__ void init_kernel(const float* __restrict__ emb, const float* __restrict__ lf)
{
    int idx = blockIdx.x * blockDim.x + threadIdx.x;
    if (idx >= 1536 * BB) return;
    int b = idx & 31, k = idx >> 5;
    float v;
    if (k < 512)       v = emb[k];
    else if (k < 1024) v = lf[(size_t)b * TT * 512 + (k - 512)];
    else             { v = 0.f; g_cT[(k - 1024) * BB + b] = 0.f; }
    g_actT[idx] = v;
}

// ---------------- gates GEMM, K-split x8, padded smem ----------------
__global__ void gates_gemm_kernel(const float* __restrict__ W_ih,
                                  const float* __restrict__ W_hh)
{
    __shared__ float ws[16 * 193];
    const int j0 = blockIdx.x * 16;
    const int base = blockIdx.y * 192;
    for (int idx = threadIdx.x; idx < 16 * 192; idx += 128) {
        int r = idx / 192, kk = idx - r * 192;
        int k = base + kk, j = j0 + r;
        ws[r * 193 + kk] = (k < 1024) ? W_ih[(size_t)j * 1024 + k]
                                      : W_hh[(size_t)j * 512 + (k - 1024)];
    }
    __syncthreads();

    int bg = threadIdx.x & 7, jj = threadIdx.x >> 3;
    const float* wr = ws + jj * 193;
    const float4* xv = (const float4*)g_actT;
    float ax = 0.f, ay = 0.f, az = 0.f, aw = 0.f;
    #pragma unroll 8
    for (int kk = 0; kk < 192; kk++) {
        float w = wr[kk];
        float4 x = xv[(base + kk) * 8 + bg];
        ax = fmaf(w, x.x, ax); ay = fmaf(w, x.y, ay);
        az = fmaf(w, x.z, az); aw = fmaf(w, x.w, aw);
    }
    ((float4*)g_gatesP[blockIdx.y])[(j0 + jj) * 8 + bg] = make_float4(ax, ay, az, aw);
}

// ---------------- LSTM pointwise (float4 over batch) ----------------
__global__ void lstm_pointwise_kernel(const float* __restrict__ b_ih,
                                      const float* __restrict__ b_hh)
{
    int idx = blockIdx.x * blockDim.x + threadIdx.x;   // 4096
    if (idx >= 512 * 8) return;
    int b4 = idx & 7, i = idx >> 3;

    float4 g4[4];
    #pragma unroll
    for (int g = 0; g < 4; g++) {
        int j = g * 512 + i;
        float bias = b_ih[j] + b_hh[j];
        float4 v = make_float4(bias, bias, bias, bias);
        #pragma unroll
        for (int p = 0; p < GKS; p++) {
            float4 x = ((const float4*)g_gatesP[p])[j * 8 + b4];
            v.x += x.x; v.y += x.y; v.z += x.z; v.w += x.w;
        }
        g4[g] = v;
    }
    float4 c = ((const float4*)g_cT)[i * 8 + b4];
    float4 hv;
    {
        float cc, h;
        #define DO_LANE(L) { \
            float si = 1.f / (1.f + __expf(-g4[0].L)); \
            float sf = 1.f / (1.f + __expf(-g4[1].L)); \
            float tg = tanhf(g4[2].L); \
            float so = 1.f / (1.f + __expf(-g4[3].L)); \
            cc = sf * c.L + si * tg; c.L = cc; \
            h = so * tanhf(cc); hv.L = h; }
        DO_LANE(x) DO_LANE(y) DO_LANE(z) DO_LANE(w)
        #undef DO_LANE
    }
    ((float4*)g_cT)[i * 8 + b4] = c;
    ((float4*)(g_actT + 1024 * BB))[i * 8 + b4] = hv;
    ((float4*)g_hcT)[i * 8 + b4] = hv;
    int b0 = b4 * 4;
    g_hRow[(b0 + 0) * 512 + i] = hv.x;
    g_hRow[(b0 + 1) * 512 + i] = hv.y;
    g_hRow[(b0 + 2) * 512 + i] = hv.z;
    g_hRow[(b0 + 3) * 512 + i] = hv.w;
}

// ------ attention partials: register-direct, warp = 4 timesteps (R12) ------
__global__ void attn_part_kernel(const float* __restrict__ lf)
{
    __shared__ float e_s[TCH];
    __shared__ __align__(16) float csh[8 * 132];
    int b = blockIdx.x & 31, hh = blockIdx.x >> 5;
    int part = blockIdx.y;
    int t0 = part * TCH;
    int tid = threadIdx.x, lane = tid & 31, w = tid >> 5;

    float4 ds4 = ((const float4*)(g_hRow + b * 512 + hh * 128))[lane];

    const float4* src = (const float4*)(lf + ((size_t)b * TT + t0) * 512 + hh * 128);
    float4 v0 = src[(size_t)(w * 4 + 0) * 128 + lane];
    float4 v1 = src[(size_t)(w * 4 + 1) * 128 + lane];
    float4 v2 = src[(size_t)(w * 4 + 2) * 128 + lane];
    float4 v3 = src[(size_t)(w * 4 + 3) * 128 + lane];

    float a0 = ds4.x * v0.x + ds4.y * v0.y + ds4.z * v0.z + ds4.w * v0.w;
    float a1 = ds4.x * v1.x + ds4.y * v1.y + ds4.z * v1.z + ds4.w * v1.w;
    float a2 = ds4.x * v2.x + ds4.y * v2.y + ds4.z * v2.z + ds4.w * v2.w;
    float a3 = ds4.x * v3.x + ds4.y * v3.y + ds4.z * v3.z + ds4.w * v3.w;
    #pragma unroll
    for (int off = 16; off; off >>= 1) {
        a0 += __shfl_xor_sync(~0u, a0, off);
        a1 += __shfl_xor_sync(~0u, a1, off);
        a2 += __shfl_xor_sync(~0u, a2, off);
        a3 += __shfl_xor_sync(~0u, a3, off);
    }
    if (lane == 0) {
        e_s[w * 4 + 0] = a0; e_s[w * 4 + 1] = a1;
        e_s[w * 4 + 2] = a2; e_s[w * 4 + 3] = a3;
    }
    __syncthreads();

    int bh = b * 4 + hh;
    if (tid < 32) {
        float e = e_s[tid];
        if (hh == 3) g_eBuf[b * TT + t0 + tid] = e;
        float m = e;
        #pragma unroll
        for (int off = 16; off; off >>= 1) m = fmaxf(m, __shfl_xor_sync(~0u, m, off));
        float p = __expf(e - m);
        e_s[tid] = p;
        float s = p;
        #pragma unroll
        for (int off = 16; off; off >>= 1) s += __shfl_xor_sync(~0u, s, off);
        if (tid == 0) { g_mP[part * 128 + bh] = m; g_sP[part * 128 + bh] = s; }
    }
    __syncthreads();

    float p0 = e_s[w * 4 + 0], p1 = e_s[w * 4 + 1];
    float p2 = e_s[w * 4 + 2], p3 = e_s[w * 4 + 3];
    float4 acc;
    acc.x = p0 * v0.x + p1 * v1.x + p2 * v2.x + p3 * v3.x;
    acc.y = p0 * v0.y + p1 * v1.y + p2 * v2.y + p3 * v3.y;
    acc.z = p0 * v0.z + p1 * v1.z + p2 * v2.z + p3 * v3.z;
    acc.w = p0 * v0.w + p1 * v1.w + p2 * v2.w + p3 * v3.w;
    ((float4*)&csh[w * 132])[lane] = acc;
    __syncthreads();

    if (tid < 128) {
        float ss = 0.f;
        #pragma unroll
        for (int q = 0; q < 8; q++) ss += csh[q * 132 + tid];
        g_ctxP[part][bh * 128 + tid] = ss;
    }
}

// ---------------- attention combine (NP=32, unchanged) ----------------
__global__ void attn_combine_kernel(float* __restrict__ attn_out)
{
    int b = blockIdx.x & 31, hh = blockIdx.x >> 5;
    int bh = b * 4 + hh;
    int tid = threadIdx.x;   // 128
    __shared__ float w_s[NP];
    __shared__ float Ms, Ss;

    if (tid < 32) {
        float m = g_mP[tid * 128 + bh];
        float sp = g_sP[tid * 128 + bh];
        float M = m;
        #pragma unroll
        for (int off = 16; off; off >>= 1) M = fmaxf(M, __shfl_xor_sync(~0u, M, off));
        float w = __expf(m - M);
        w_s[tid] = w;
        float s = sp * w;
        #pragma unroll
        for (int off = 16; off; off >>= 1) s += __shfl_xor_sync(~0u, s, off);
        if (tid == 0) { Ms = M; Ss = s; }
    }
    __syncthreads();
    float inv = 1.f / Ss;
    float M = Ms;

    float ctx = 0.f;
    #pragma unroll
    for (int p = 0; p < NP; p++) ctx = fmaf(g_ctxP[p][bh * 128 + tid], w_s[p], ctx);
    ctx *= inv;
    int d = hh * 128 + tid;
    g_actT[(512 + d) * BB + b] = ctx;
    g_hcT[(512 + d) * BB + b] = ctx;

    if (hh == 3) {
        #pragma unroll
        for (int i = 0; i < 8; i++) {
            int t = tid + i * 128;
            __stcs(&attn_out[(size_t)b * TT + t], __expf(g_eBuf[b * TT + t] - M) * inv);
        }
    }
}

// ------- predict_hid split GEMM: K-split x8, smem-staged weights -------
__global__ void hid_split_kernel(const float* __restrict__ Wp)
{
    __shared__ float ws[16 * 129];
    const int j0 = blockIdx.x * 16;       // 32 j-tiles
    const int base = blockIdx.y * 128;    // 8 K-parts
    for (int idx = threadIdx.x; idx < 16 * 128; idx += 128) {
        int r = idx >> 7, kk = idx & 127;
        ws[r * 129 + kk] = Wp[(size_t)(j0 + r) * 1024 + base + kk];
    }
    __syncthreads();

    int bg = threadIdx.x & 7, jj = threadIdx.x >> 3;
    const float* wr = ws + jj * 129;
    const float4* xv = (const float4*)g_hcT;
    float ax = 0.f, ay = 0.f, az = 0.f, aw = 0.f;
    #pragma unroll 8
    for (int kk = 0; kk < 128; kk++) {
        float w = wr[kk];
        float4 x = xv[(base + kk) * 8 + bg];
        ax = fmaf(w, x.x, ax); ay = fmaf(w, x.y, ay);
        az = fmaf(w, x.z, az); aw = fmaf(w, x.w, aw);
    }
    ((float4*)g_hidP[blockIdx.y])[(j0 + jj) * 8 + bg] = make_float4(ax, ay, az, aw);
}

// ------- hid reduce: sum 8 partials + bias + relu -------
__global__ void hid_reduce_kernel(const float* __restrict__ bp)
{
    int idx = blockIdx.x * blockDim.x + threadIdx.x;   // 4096 float4 items
    if (idx >= 512 * 8) return;
    int j = idx >> 3;
    float4 v = make_float4(0.f, 0.f, 0.f, 0.f);
    #pragma unroll
    for (int p = 0; p < HKS; p++) {
        float4 x = ((const float4*)g_hidP[p])[idx];
        v.x += x.x; v.y += x.y; v.z += x.z; v.w += x.w;
    }
    float bias = bp[j];
    v.x = fmaxf(v.x + bias, 0.f); v.y = fmaxf(v.y + bias, 0.f);
    v.z = fmaxf(v.z + bias, 0.f); v.w = fmaxf(v.w + bias, 0.f);
    ((float4*)g_hidT)[idx] = v;
}

// ---------------- logits GEMM, K-split x4, padded smem ----------------
__global__ void logits_gemm_kernel(const float* __restrict__ Wc)
{
    __shared__ float ws[16 * 129];
    const int j0 = blockIdx.x * 16;
    const int base = blockIdx.y * 128;
    for (int idx = threadIdx.x; idx < 16 * 128; idx += 128) {
        int r = idx >> 7, kk = idx & 127;
        int j = j0 + r;
        ws[r * 129 + kk] = (j < VV) ? Wc[(size_t)j * 512 + base + kk] : 0.f;
    }
    __syncthreads();

    int bg = threadIdx.x & 7, jj = threadIdx.x >> 3;
    int j = j0 + jj;
    const float* wr = ws + jj * 129;
    const float4* xv = (const float4*)g_hidT;
    float ax = 0.f, ay = 0.f, az = 0.f, aw = 0.f;
    #pragma unroll 8
    for (int kk = 0; kk < 128; kk++) {
        float w = wr[kk];
        float4 x = xv[(base + kk) * 8 + bg];
        ax = fmaf(w, x.x, ax); ay = fmaf(w, x.y, ay);
        az = fmaf(w, x.z, az); aw = fmaf(w, x.w, aw);
    }
    if (j < VV) {
        float* dst = g_logitsP[blockIdx.y];
        int b0 = bg * 4;
        dst[(size_t)(b0 + 0) * JPAD + j] = ax;
        dst[(size_t)(b0 + 1) * JPAD + j] = ay;
        dst[(size_t)(b0 + 2) * JPAD + j] = az;
        dst[(size_t)(b0 + 3) * JPAD + j] = aw;
    }
}

// ------- log_softmax + argmax + pred row + next embedding -----
__global__ void lsm_kernel(const float* __restrict__ bc, const float* __restrict__ emb,
                           float* __restrict__ out_pred)
{
    int b = blockIdx.x;
    int tid = threadIdx.x;   // 1024
    __shared__ float v_s[VV];
    __shared__ float sv[1024];
    __shared__ int   si[1024];
    __shared__ int   tok_s;

    const float4* p0 = (const float4*)(g_logitsP[0] + (size_t)b * JPAD);
    const float4* p1 = (const float4*)(g_logitsP[1] + (size_t)b * JPAD);
    const float4* p2 = (const float4*)(g_logitsP[2] + (size_t)b * JPAD);
    const float4* p3 = (const float4*)(g_logitsP[3] + (size_t)b * JPAD);
    const float4* bcv = (const float4*)bc;
    for (int j4 = tid; j4 < VV / 4; j4 += 1024) {
        float4 a = p0[j4], c = p1[j4], d = p2[j4], e = p3[j4], f = bcv[j4];
        float4 r;
        r.x = a.x + c.x + d.x + e.x + f.x;
        r.y = a.y + c.y + d.y + e.y + f.y;
        r.z = a.z + c.z + d.z + e.z + f.z;
        r.w = a.w + c.w + d.w + e.w + f.w;
        ((float4*)v_s)[j4] = r;
    }
    __syncthreads();

    float m = -1e30f; int mi = VV;
    for (int j = tid; j < VV; j += 1024) {
        float v = v_s[j];
        if (v > m) { m = v; mi = j; }
    }
    sv[tid] = m; si[tid] = mi; __syncthreads();
    for (int st = 512; st; st >>= 1) {
        if (tid < st) {
            float v2 = sv[tid + st]; int i2 = si[tid + st];
            if (v2 > sv[tid] || (v2 == sv[tid] && i2 < si[tid])) { sv[tid] = v2; si[tid] = i2; }
        }
        __syncthreads();
    }
    float mm = sv[0];
    if (tid == 0) tok_s = si[0];
    __syncthreads();

    float s = 0.f;
    for (int j = tid; j < VV; j += 1024) s += __expf(v_s[j] - mm);
    sv[tid] = s; __syncthreads();
    for (int st = 512; st; st >>= 1) { if (tid < st) sv[tid] += sv[tid + st]; __syncthreads(); }
    float lse = mm + logf(sv[0]);

    float4* row = (float4*)(out_pred + (size_t)b * VV);
    for (int j4 = tid; j4 < VV / 4; j4 += 1024) {
        float4 v = ((float4*)v_s)[j4];
        v.x -= lse; v.y -= lse; v.z -= lse; v.w -= lse;
        __stcs(&row[j4], v);
    }

    int tok = tok_s;
    if (tid < 512) g_actT[tid * BB + b] = emb[(size_t)tok * 512 + tid];
}

// ---------------- launcher ----------------
extern "C" void kernel_launch(void* const* d_in, const int* in_sizes, int n_in,
                              void* d_out, int out_size)
{
    const float* lf   = (const float*)d_in[0];
    const float* emb  = (const float*)d_in[1];
    const float* W_ih = (const float*)d_in[2];
    const float* W_hh = (const float*)d_in[3];
    const float* b_ih = (const float*)d_in[4];
    const float* b_hh = (const float*)d_in[5];
    const float* Wp   = (const float*)d_in[6];
    const float* bp   = (const float*)d_in[7];
    const float* Wc   = (const float*)d_in[8];
    const float* bc   = (const float*)d_in[9];

    float* out      = (float*)d_out;
    float* out_pred = out;
    float* out_attn = out + (size_t)STEPS * BB * VV;

    init_kernel<<<192, 256>>>(emb, lf);

    for (int s = 0; s < STEPS; s++) {
        gates_gemm_kernel<<<dim3(128, GKS), 128>>>(W_ih, W_hh);
        lstm_pointwise_kernel<<<16, 256>>>(b_ih, b_hh);
        attn_part_kernel<<<dim3(128, NP), 256>>>(lf);
        attn_combine_kernel<<<128, 128>>>(out_attn + (size_t)s * BB * TT);
        hid_split_kernel<<<dim3(32, HKS), 128>>>(Wp);
        hid_reduce_kernel<<<16, 256>>>(bp);
        logits_gemm_kernel<<<dim3(313, LKS), 128>>>(Wc);
        lsm_kernel<<<32, 1024>>>(bc, emb, out_pred + (size_t)s * BB * VV);
    }
}